// round 12
// baseline (speedup 1.0000x reference)
#include <cuda_runtime.h>
#include <math.h>
#include <stdint.h>

// Problem shape (fixed by the dataset): N=100000, E=800000, F_IN=96, H=128, C=64.
#define MAXN 100000
#define MAXE 800000
#define FIN 96
#define HID 128
#define COUT 64
#define NBLK ((MAXN + 255) / 256)

// Scratch (static __device__ — no allocations allowed in kernel_launch).
__device__ float4 g_dinv4[(MAXN + 3) / 4];            // d^{-1/2}
__device__ float4 g_aggx_4[(size_t)MAXN * FIN / 4];   // Â·x  (96-wide)
__device__ float4 g_h1b_4[(size_t)MAXN * HID / 4];    // relu(aggx@W1+b1)
__device__ float4 g_h2_4[(size_t)MAXN * COUT / 4];    // h1b@W2
__device__ int    g_src[MAXE];                        // edge src as int32
__device__ int    g_dst[MAXE];                        // edge dst as int32
__device__ int    g_cnt[MAXN];                        // in-degree (no self loop)
__device__ int    g_off[MAXN];                        // row offsets; after
                                                      // scatter: row END
__device__ int    g_bsum[NBLK];
__device__ int    g_bbase[NBLK];
__device__ int    g_eidx[MAXE];                       // CSR: src per slot
__device__ float  g_ew[MAXE];                         // CSR: dinv[src] per slot
__device__ unsigned g_anyodd;

#define g_dinv ((float*)g_dinv4)
#define g_aggx ((float*)g_aggx_4)
#define g_h1b  ((float*)g_h1b_4)
#define g_h2   ((float*)g_h2_4)

// ---------------------------------------------------------------------------
// TF32 helpers
// ---------------------------------------------------------------------------
__device__ __forceinline__ uint32_t f2tf32(float f) {
    uint32_t r;
    asm("cvt.rna.tf32.f32 %0, %1;" : "=r"(r) : "f"(f));
    return r;
}

__device__ __forceinline__ void mma_tf32(float* d, const uint32_t* a,
                                         uint32_t b0, uint32_t b1) {
    asm volatile(
        "mma.sync.aligned.m16n8k8.row.col.f32.tf32.tf32.f32 "
        "{%0,%1,%2,%3}, {%4,%5,%6,%7}, {%8,%9}, {%0,%1,%2,%3};"
        : "+f"(d[0]), "+f"(d[1]), "+f"(d[2]), "+f"(d[3])
        : "r"(a[0]), "r"(a[1]), "r"(a[2]), "r"(a[3]), "r"(b0), "r"(b1));
}

// ---------------------------------------------------------------------------
// Zero degree counters; one dedicated block probes the edge-index dtype.
// int64 (LE, ids < 2^31): odd 32-bit words are all 0; int32: they are real
// src ids (random in [0,N)) and cannot all be zero over 4096 samples.
// ---------------------------------------------------------------------------
__global__ void init_detect_kernel(const unsigned* __restrict__ w, int E,
                                   int N) {
    int i = blockIdx.x * blockDim.x + threadIdx.x;
    if (i == 0) g_anyodd = 0u;
    if (i < N) g_cnt[i] = 0;
    if (blockIdx.x == 1) {
        int limit = (E < 4096) ? E : 4096;
        unsigned acc = 0u;
        for (int t = threadIdx.x; t < limit; t += blockDim.x)
            acc |= w[2 * t + 1];
        for (int o = 16; o > 0; o >>= 1)
            acc |= __shfl_xor_sync(0xFFFFFFFFu, acc, o);
        if ((threadIdx.x & 31) == 0 && acc) atomicOr(&g_anyodd, acc);
    }
}

// Convert indices to int32 once AND count in-degrees in the same pass.
__global__ void idx_convert_count_kernel(const void* __restrict__ ei, int E) {
    int e = blockIdx.x * blockDim.x + threadIdx.x;
    if (e >= E) return;
    int s, d;
    if (g_anyodd) {          // int32 layout
        const int* p = (const int*)ei;
        s = p[e]; d = p[E + e];
    } else {                 // int64 layout
        const long long* p = (const long long*)ei;
        s = (int)p[e]; d = (int)p[E + e];
    }
    g_src[e] = s;
    g_dst[e] = d;
    atomicAdd(&g_cnt[d], 1);
}

// ---------------------------------------------------------------------------
// Exclusive scan of g_cnt into g_off (3 stages), then scatter to CSR.
// ---------------------------------------------------------------------------
__global__ void scanA_kernel(int N) {
    __shared__ int sm[256];
    int i = blockIdx.x * 256 + threadIdx.x;
    int v = (i < N) ? g_cnt[i] : 0;
    sm[threadIdx.x] = v;
    __syncthreads();
#pragma unroll
    for (int o = 1; o < 256; o <<= 1) {
        int t = (threadIdx.x >= o) ? sm[threadIdx.x - o] : 0;
        __syncthreads();
        sm[threadIdx.x] += t;
        __syncthreads();
    }
    if (i < N) g_off[i] = sm[threadIdx.x] - v;
    if (threadIdx.x == 255) g_bsum[blockIdx.x] = sm[255];
}

__global__ void scanB_kernel(int nblk) {
    __shared__ int sm[512];
    int i = threadIdx.x;
    int v = (i < nblk) ? g_bsum[i] : 0;
    sm[i] = v;
    __syncthreads();
#pragma unroll
    for (int o = 1; o < 512; o <<= 1) {
        int t = (i >= o) ? sm[i - o] : 0;
        __syncthreads();
        sm[i] += t;
        __syncthreads();
    }
    if (i < nblk) g_bbase[i] = sm[i] - v;
}

__global__ void scanC_kernel(int N) {
    int i = blockIdx.x * blockDim.x + threadIdx.x;
    if (i >= N) return;
    g_off[i] += g_bbase[i >> 8];
    g_dinv[i] = rsqrtf((float)(g_cnt[i] + 1));
}

// Scatter edges into CSR slots. atomicAdd directly on g_off: afterwards
// g_off[d] == row end; agg kernels recover beg = g_off[d] - g_cnt[d].
__global__ void scatter_kernel(int E) {
    int e = blockIdx.x * blockDim.x + threadIdx.x;
    if (e >= E) return;
    int s = g_src[e], d = g_dst[e];
    int pos = atomicAdd(&g_off[d], 1);
    g_eidx[pos] = s;
    g_ew[pos] = g_dinv[s];
}

// ---------------------------------------------------------------------------
// Input-space aggregation (CSR, zero atomics): aggx = Â·x  (96-wide).
// One warp per dst; lanes 0..23 each own one float4. Edge loop unrolled x4
// with independent accumulators (L2-hit latency is the binding chain).
// ---------------------------------------------------------------------------
__global__ void aggx_csr_kernel(const float* __restrict__ x, int N) {
    int gid = blockIdx.x * blockDim.x + threadIdx.x;
    int d = gid >> 5;
    int lane = gid & 31;
    if (d >= N || lane >= 24) return;

    int end = g_off[d];
    int beg = end - g_cnt[d];

    float4 a0 = make_float4(0.f, 0.f, 0.f, 0.f);
    float4 a1 = make_float4(0.f, 0.f, 0.f, 0.f);
    float4 a2 = make_float4(0.f, 0.f, 0.f, 0.f);
    float4 a3 = make_float4(0.f, 0.f, 0.f, 0.f);
    int j = beg;
    for (; j + 3 < end; j += 4) {
        int s0 = g_eidx[j],     s1 = g_eidx[j + 1];
        int s2 = g_eidx[j + 2], s3 = g_eidx[j + 3];
        float w0 = g_ew[j],     w1 = g_ew[j + 1];
        float w2 = g_ew[j + 2], w3 = g_ew[j + 3];
        float4 v0 = *(const float4*)(x + (size_t)s0 * FIN + lane * 4);
        float4 v1 = *(const float4*)(x + (size_t)s1 * FIN + lane * 4);
        float4 v2 = *(const float4*)(x + (size_t)s2 * FIN + lane * 4);
        float4 v3 = *(const float4*)(x + (size_t)s3 * FIN + lane * 4);
        a0.x = fmaf(v0.x, w0, a0.x); a0.y = fmaf(v0.y, w0, a0.y);
        a0.z = fmaf(v0.z, w0, a0.z); a0.w = fmaf(v0.w, w0, a0.w);
        a1.x = fmaf(v1.x, w1, a1.x); a1.y = fmaf(v1.y, w1, a1.y);
        a1.z = fmaf(v1.z, w1, a1.z); a1.w = fmaf(v1.w, w1, a1.w);
        a2.x = fmaf(v2.x, w2, a2.x); a2.y = fmaf(v2.y, w2, a2.y);
        a2.z = fmaf(v2.z, w2, a2.z); a2.w = fmaf(v2.w, w2, a2.w);
        a3.x = fmaf(v3.x, w3, a3.x); a3.y = fmaf(v3.y, w3, a3.y);
        a3.z = fmaf(v3.z, w3, a3.z); a3.w = fmaf(v3.w, w3, a3.w);
    }
    for (; j < end; j++) {
        int s0 = g_eidx[j];
        float w0 = g_ew[j];
        float4 v0 = *(const float4*)(x + (size_t)s0 * FIN + lane * 4);
        a0.x = fmaf(v0.x, w0, a0.x); a0.y = fmaf(v0.y, w0, a0.y);
        a0.z = fmaf(v0.z, w0, a0.z); a0.w = fmaf(v0.w, w0, a0.w);
    }
    a0.x += a1.x + a2.x + a3.x;
    a0.y += a1.y + a2.y + a3.y;
    a0.z += a1.z + a2.z + a3.z;
    a0.w += a1.w + a2.w + a3.w;

    float dd = g_dinv[d];
    float dd2 = dd * dd;
    float4 xd = *(const float4*)(x + (size_t)d * FIN + lane * 4);
    float4 r;
    r.x = fmaf(a0.x, dd, xd.x * dd2);
    r.y = fmaf(a0.y, dd, xd.y * dd2);
    r.z = fmaf(a0.z, dd, xd.z * dd2);
    r.w = fmaf(a0.w, dd, xd.w * dd2);
    g_aggx_4[(size_t)d * 24 + lane] = r;
}

// ---------------------------------------------------------------------------
// GEMM1 (TF32): h1b[N,128] = relu(aggx[N,96] @ W1[96,128] + b1); also emb.
// ---------------------------------------------------------------------------
__global__ void gemm1_tc_kernel(const float* __restrict__ W1,
                                const float* __restrict__ b1,
                                float* __restrict__ emb, int N) {
    __shared__ __align__(16) uint32_t Xs[128][36];
    __shared__ __align__(16) uint32_t Ws[32][132];
    const int tid = threadIdx.x;
    const int wid = tid >> 5;
    const int lane = tid & 31;
    const int gidl = lane >> 2;
    const int tig = lane & 3;
    const int warp_m = (wid >> 1) * 32;
    const int warp_n = (wid & 1) * 64;
    const int rowBase = blockIdx.x * 128;

    float acc[2][8][4];
#pragma unroll
    for (int mt = 0; mt < 2; mt++)
#pragma unroll
        for (int nt = 0; nt < 8; nt++)
#pragma unroll
            for (int i = 0; i < 4; i++) acc[mt][nt][i] = 0.0f;

    for (int k0 = 0; k0 < FIN; k0 += 32) {
#pragma unroll
        for (int t = tid; t < 1024; t += 256) {
            int r = t >> 3, c = (t & 7) * 4;
            int gr = rowBase + r;
            float4 v = make_float4(0.f, 0.f, 0.f, 0.f);
            if (gr < N) v = *(const float4*)(g_aggx + (size_t)gr * FIN + k0 + c);
            Xs[r][c + 0] = f2tf32(v.x);
            Xs[r][c + 1] = f2tf32(v.y);
            Xs[r][c + 2] = f2tf32(v.z);
            Xs[r][c + 3] = f2tf32(v.w);
        }
#pragma unroll
        for (int t = tid; t < 1024; t += 256) {
            int r = t >> 5, c = (t & 31) * 4;
            float4 v = *(const float4*)(W1 + (size_t)(k0 + r) * HID + c);
            Ws[r][c + 0] = f2tf32(v.x);
            Ws[r][c + 1] = f2tf32(v.y);
            Ws[r][c + 2] = f2tf32(v.z);
            Ws[r][c + 3] = f2tf32(v.w);
        }
        __syncthreads();

#pragma unroll
        for (int kk = 0; kk < 4; kk++) {
            int k8 = kk * 8;
            uint32_t a[2][4];
#pragma unroll
            for (int mt = 0; mt < 2; mt++) {
                int mb = warp_m + mt * 16;
                a[mt][0] = Xs[mb + gidl][k8 + tig];
                a[mt][1] = Xs[mb + gidl + 8][k8 + tig];
                a[mt][2] = Xs[mb + gidl][k8 + tig + 4];
                a[mt][3] = Xs[mb + gidl + 8][k8 + tig + 4];
            }
#pragma unroll
            for (int nt = 0; nt < 8; nt++) {
                int nb = warp_n + nt * 8;
                uint32_t b0 = Ws[k8 + tig][nb + gidl];
                uint32_t b1v = Ws[k8 + tig + 4][nb + gidl];
                mma_tf32(acc[0][nt], a[0], b0, b1v);
                mma_tf32(acc[1][nt], a[1], b0, b1v);
            }
        }
        __syncthreads();
    }

#pragma unroll
    for (int mt = 0; mt < 2; mt++) {
#pragma unroll
        for (int nt = 0; nt < 8; nt++) {
            int col = warp_n + nt * 8 + 2 * tig;
            float2 bb = *(const float2*)(b1 + col);
            int r0 = rowBase + warp_m + mt * 16 + gidl;
            if (r0 < N) {
                float2 v = make_float2(fmaxf(acc[mt][nt][0] + bb.x, 0.f),
                                       fmaxf(acc[mt][nt][1] + bb.y, 0.f));
                *(float2*)(g_h1b + (size_t)r0 * HID + col) = v;
                if (emb) *(float2*)(emb + (size_t)r0 * HID + col) = v;
            }
            if (r0 + 8 < N) {
                float2 v = make_float2(fmaxf(acc[mt][nt][2] + bb.x, 0.f),
                                       fmaxf(acc[mt][nt][3] + bb.y, 0.f));
                *(float2*)(g_h1b + (size_t)(r0 + 8) * HID + col) = v;
                if (emb) *(float2*)(emb + (size_t)(r0 + 8) * HID + col) = v;
            }
        }
    }
}

// ---------------------------------------------------------------------------
// GEMM2 (TF32): g_h2[N,64] = g_h1b[N,128] @ W2[128,64]
// ---------------------------------------------------------------------------
__global__ void gemm2_tc_kernel(const float* __restrict__ W2, int N) {
    __shared__ __align__(16) uint32_t Xs[128][36];
    __shared__ __align__(16) uint32_t Ws[32][68];
    const int tid = threadIdx.x;
    const int wid = tid >> 5;
    const int lane = tid & 31;
    const int gidl = lane >> 2;
    const int tig = lane & 3;
    const int warp_m = wid * 16;
    const int rowBase = blockIdx.x * 128;

    float acc[8][4];
#pragma unroll
    for (int nt = 0; nt < 8; nt++)
#pragma unroll
        for (int i = 0; i < 4; i++) acc[nt][i] = 0.0f;

    for (int k0 = 0; k0 < HID; k0 += 32) {
#pragma unroll
        for (int t = tid; t < 1024; t += 256) {
            int r = t >> 3, c = (t & 7) * 4;
            int gr = rowBase + r;
            float4 v = make_float4(0.f, 0.f, 0.f, 0.f);
            if (gr < N) v = *(const float4*)(g_h1b + (size_t)gr * HID + k0 + c);
            Xs[r][c + 0] = f2tf32(v.x);
            Xs[r][c + 1] = f2tf32(v.y);
            Xs[r][c + 2] = f2tf32(v.z);
            Xs[r][c + 3] = f2tf32(v.w);
        }
#pragma unroll
        for (int t = tid; t < 512; t += 256) {
            int r = t >> 4, c = (t & 15) * 4;
            float4 v = *(const float4*)(W2 + (size_t)(k0 + r) * COUT + c);
            Ws[r][c + 0] = f2tf32(v.x);
            Ws[r][c + 1] = f2tf32(v.y);
            Ws[r][c + 2] = f2tf32(v.z);
            Ws[r][c + 3] = f2tf32(v.w);
        }
        __syncthreads();

#pragma unroll
        for (int kk = 0; kk < 4; kk++) {
            int k8 = kk * 8;
            uint32_t a[4];
            a[0] = Xs[warp_m + gidl][k8 + tig];
            a[1] = Xs[warp_m + gidl + 8][k8 + tig];
            a[2] = Xs[warp_m + gidl][k8 + tig + 4];
            a[3] = Xs[warp_m + gidl + 8][k8 + tig + 4];
#pragma unroll
            for (int nt = 0; nt < 8; nt++) {
                int nb = nt * 8;
                uint32_t b0 = Ws[k8 + tig][nb + gidl];
                uint32_t b1 = Ws[k8 + tig + 4][nb + gidl];
                mma_tf32(acc[nt], a, b0, b1);
            }
        }
        __syncthreads();
    }

#pragma unroll
    for (int nt = 0; nt < 8; nt++) {
        int col = nt * 8 + 2 * tig;
        int r0 = rowBase + warp_m + gidl;
        if (r0 < N)
            *(float2*)(g_h2 + (size_t)r0 * COUT + col) =
                make_float2(acc[nt][0], acc[nt][1]);
        if (r0 + 8 < N)
            *(float2*)(g_h2 + (size_t)(r0 + 8) * COUT + col) =
                make_float2(acc[nt][2], acc[nt][3]);
    }
}

// ---------------------------------------------------------------------------
// Layer-2 aggregation (CSR) + bias + fused warp log_softmax. Unrolled x4.
// ---------------------------------------------------------------------------
__global__ void agg2_csr_kernel(const float* __restrict__ b2,
                                float* __restrict__ out, int N) {
    int gid = blockIdx.x * blockDim.x + threadIdx.x;
    int d = gid >> 5;
    int lane = gid & 31;
    if (d >= N) return;

    int end = g_off[d];
    int beg = end - g_cnt[d];

    float2 a0 = make_float2(0.f, 0.f);
    float2 a1 = make_float2(0.f, 0.f);
    float2 a2 = make_float2(0.f, 0.f);
    float2 a3 = make_float2(0.f, 0.f);
    int j = beg;
    for (; j + 3 < end; j += 4) {
        int s0 = g_eidx[j],     s1 = g_eidx[j + 1];
        int s2 = g_eidx[j + 2], s3 = g_eidx[j + 3];
        float w0 = g_ew[j],     w1 = g_ew[j + 1];
        float w2 = g_ew[j + 2], w3 = g_ew[j + 3];
        float2 v0 = *(const float2*)(g_h2 + (size_t)s0 * COUT + lane * 2);
        float2 v1 = *(const float2*)(g_h2 + (size_t)s1 * COUT + lane * 2);
        float2 v2 = *(const float2*)(g_h2 + (size_t)s2 * COUT + lane * 2);
        float2 v3 = *(const float2*)(g_h2 + (size_t)s3 * COUT + lane * 2);
        a0.x = fmaf(v0.x, w0, a0.x); a0.y = fmaf(v0.y, w0, a0.y);
        a1.x = fmaf(v1.x, w1, a1.x); a1.y = fmaf(v1.y, w1, a1.y);
        a2.x = fmaf(v2.x, w2, a2.x); a2.y = fmaf(v2.y, w2, a2.y);
        a3.x = fmaf(v3.x, w3, a3.x); a3.y = fmaf(v3.y, w3, a3.y);
    }
    for (; j < end; j++) {
        int s0 = g_eidx[j];
        float w0 = g_ew[j];
        float2 v0 = *(const float2*)(g_h2 + (size_t)s0 * COUT + lane * 2);
        a0.x = fmaf(v0.x, w0, a0.x); a0.y = fmaf(v0.y, w0, a0.y);
    }
    a0.x += a1.x + a2.x + a3.x;
    a0.y += a1.y + a2.y + a3.y;

    float dd = g_dinv[d];
    float dd2 = dd * dd;
    float2 hd = *(const float2*)(g_h2 + (size_t)d * COUT + lane * 2);
    float2 bb = *(const float2*)(b2 + lane * 2);
    float2 o;
    o.x = fmaf(a0.x, dd, fmaf(hd.x, dd2, bb.x));
    o.y = fmaf(a0.y, dd, fmaf(hd.y, dd2, bb.y));

    float m = fmaxf(o.x, o.y);
#pragma unroll
    for (int off = 16; off > 0; off >>= 1)
        m = fmaxf(m, __shfl_xor_sync(0xFFFFFFFFu, m, off));
    float sum = expf(o.x - m) + expf(o.y - m);
#pragma unroll
    for (int off = 16; off > 0; off >>= 1)
        sum += __shfl_xor_sync(0xFFFFFFFFu, sum, off);
    float l = logf(sum) + m;
    *(float2*)(out + (size_t)d * COUT + lane * 2) =
        make_float2(o.x - l, o.y - l);
}

// ---------------------------------------------------------------------------
extern "C" void kernel_launch(void* const* d_in, const int* in_sizes, int n_in,
                              void* d_out, int out_size) {
    const float* x  = (const float*)d_in[0];
    const float* W1 = (const float*)d_in[1];
    const float* b1 = (const float*)d_in[2];
    const float* W2 = (const float*)d_in[3];
    const float* b2 = (const float*)d_in[4];
    const void*  ei = d_in[5];

    const int H   = in_sizes[2];                 // 128
    const int Fin = in_sizes[1] / H;             // 96
    const int C   = in_sizes[4];                 // 64
    const int N   = in_sizes[0] / Fin;           // 100000
    const int E   = in_sizes[5] / 2;             // 800000

    float* out = (float*)d_out;
    float* emb = ((long long)out_size >= (long long)N * (C + H))
                     ? out + (size_t)N * C
                     : nullptr;

    const int T = 256;
    const int nblk = (N + 255) / 256;

    // Init + dtype detect, then convert+count (src/dst materialized ONCE —
    // the R11 direct-reread variant regressed; this is the proven path).
    init_detect_kernel<<<(N + T - 1) / T, T>>>((const unsigned*)ei, E, N);
    idx_convert_count_kernel<<<(E + T - 1) / T, T>>>(ei, E);

    // CSR build
    scanA_kernel<<<nblk, 256>>>(N);
    scanB_kernel<<<1, 512>>>(nblk);
    scanC_kernel<<<(N + T - 1) / T, T>>>(N);
    scatter_kernel<<<(E + T - 1) / T, T>>>(E);

    // Layer 1: aggregate in input space (96-wide), then GEMM with fused
    // bias+relu+embedding epilogue.
    aggx_csr_kernel<<<(int)(((long long)N * 32 + T - 1) / T), T>>>(x, N);
    gemm1_tc_kernel<<<(N + 127) / 128, 256>>>(W1, b1, emb, N);

    // Layer 2: GEMM then aggregate in output space (64-wide) with fused
    // bias + log_softmax.
    gemm2_tc_kernel<<<(N + 127) / 128, 256>>>(W2, N);
    agg2_csr_kernel<<<(int)(((long long)N * 32 + T - 1) / T), T>>>(b2, out, N);
}

// round 13
// speedup vs baseline: 1.1195x; 1.1195x over previous
#include <cuda_runtime.h>
#include <math.h>
#include <stdint.h>

// Problem shape (fixed by the dataset): N=100000, E=800000, F_IN=96, H=128, C=64.
#define MAXN 100000
#define MAXE 800000
#define FIN 96
#define HID 128
#define COUT 64
#define NBLK ((MAXN + 255) / 256)

// Scratch (static __device__ — no allocations allowed in kernel_launch).
__device__ float4 g_dinv4[(MAXN + 3) / 4];            // d^{-1/2}
__device__ float4 g_aggx_4[(size_t)MAXN * FIN / 4];   // Â·x  (96-wide)
__device__ float4 g_h1b_4[(size_t)MAXN * HID / 4];    // relu(aggx@W1+b1)
__device__ float4 g_h2_4[(size_t)MAXN * COUT / 4];    // h1b@W2
__device__ int    g_src[MAXE];                        // edge src as int32
__device__ int    g_dst[MAXE];                        // edge dst as int32
__device__ int    g_cnt[MAXN];                        // in-degree (no self loop)
__device__ int    g_off[MAXN];                        // row offsets; after
                                                      // scatter: row END
__device__ int    g_bsum[NBLK];
__device__ int    g_bbase[NBLK];
__device__ int    g_eidx[MAXE];                       // CSR: src per slot
__device__ float  g_ew[MAXE];                         // CSR: dinv[src] per slot
__device__ unsigned g_anyodd;

#define g_dinv ((float*)g_dinv4)
#define g_aggx ((float*)g_aggx_4)
#define g_h1b  ((float*)g_h1b_4)
#define g_h2   ((float*)g_h2_4)

// ---------------------------------------------------------------------------
// TF32 helpers
// ---------------------------------------------------------------------------
__device__ __forceinline__ uint32_t f2tf32(float f) {
    uint32_t r;
    asm("cvt.rna.tf32.f32 %0, %1;" : "=r"(r) : "f"(f));
    return r;
}

__device__ __forceinline__ void mma_tf32(float* d, const uint32_t* a,
                                         uint32_t b0, uint32_t b1) {
    asm volatile(
        "mma.sync.aligned.m16n8k8.row.col.f32.tf32.tf32.f32 "
        "{%0,%1,%2,%3}, {%4,%5,%6,%7}, {%8,%9}, {%0,%1,%2,%3};"
        : "+f"(d[0]), "+f"(d[1]), "+f"(d[2]), "+f"(d[3])
        : "r"(a[0]), "r"(a[1]), "r"(a[2]), "r"(a[3]), "r"(b0), "r"(b1));
}

// ---------------------------------------------------------------------------
// Zero degree counters; one dedicated block probes the edge-index dtype.
// int64 (LE, ids < 2^31): odd 32-bit words are all 0; int32: they are real
// src ids (random in [0,N)) and cannot all be zero over 4096 samples.
// ---------------------------------------------------------------------------
__global__ void init_detect_kernel(const unsigned* __restrict__ w, int E,
                                   int N) {
    int i = blockIdx.x * blockDim.x + threadIdx.x;
    if (i == 0) g_anyodd = 0u;
    if (i < N) g_cnt[i] = 0;
    if (blockIdx.x == 1) {
        int limit = (E < 4096) ? E : 4096;
        unsigned acc = 0u;
        for (int t = threadIdx.x; t < limit; t += blockDim.x)
            acc |= w[2 * t + 1];
        for (int o = 16; o > 0; o >>= 1)
            acc |= __shfl_xor_sync(0xFFFFFFFFu, acc, o);
        if ((threadIdx.x & 31) == 0 && acc) atomicOr(&g_anyodd, acc);
    }
}

// Convert indices to int32 once AND count in-degrees in the same pass.
__global__ void idx_convert_count_kernel(const void* __restrict__ ei, int E) {
    int e = blockIdx.x * blockDim.x + threadIdx.x;
    if (e >= E) return;
    int s, d;
    if (g_anyodd) {          // int32 layout
        const int* p = (const int*)ei;
        s = p[e]; d = p[E + e];
    } else {                 // int64 layout
        const long long* p = (const long long*)ei;
        s = (int)p[e]; d = (int)p[E + e];
    }
    g_src[e] = s;
    g_dst[e] = d;
    atomicAdd(&g_cnt[d], 1);
}

// ---------------------------------------------------------------------------
// Exclusive scan of g_cnt into g_off (3 stages), then scatter to CSR.
// ---------------------------------------------------------------------------
__global__ void scanA_kernel(int N) {
    __shared__ int sm[256];
    int i = blockIdx.x * 256 + threadIdx.x;
    int v = (i < N) ? g_cnt[i] : 0;
    sm[threadIdx.x] = v;
    __syncthreads();
#pragma unroll
    for (int o = 1; o < 256; o <<= 1) {
        int t = (threadIdx.x >= o) ? sm[threadIdx.x - o] : 0;
        __syncthreads();
        sm[threadIdx.x] += t;
        __syncthreads();
    }
    if (i < N) g_off[i] = sm[threadIdx.x] - v;
    if (threadIdx.x == 255) g_bsum[blockIdx.x] = sm[255];
}

__global__ void scanB_kernel(int nblk) {
    __shared__ int sm[512];
    int i = threadIdx.x;
    int v = (i < nblk) ? g_bsum[i] : 0;
    sm[i] = v;
    __syncthreads();
#pragma unroll
    for (int o = 1; o < 512; o <<= 1) {
        int t = (i >= o) ? sm[i - o] : 0;
        __syncthreads();
        sm[i] += t;
        __syncthreads();
    }
    if (i < nblk) g_bbase[i] = sm[i] - v;
}

__global__ void scanC_kernel(int N) {
    int i = blockIdx.x * blockDim.x + threadIdx.x;
    if (i >= N) return;
    g_off[i] += g_bbase[i >> 8];
    g_dinv[i] = rsqrtf((float)(g_cnt[i] + 1));
}

// Scatter edges into CSR slots. atomicAdd directly on g_off: afterwards
// g_off[d] == row end; agg kernels recover beg = g_off[d] - g_cnt[d].
__global__ void scatter_kernel(int E) {
    int e = blockIdx.x * blockDim.x + threadIdx.x;
    if (e >= E) return;
    int s = g_src[e], d = g_dst[e];
    int pos = atomicAdd(&g_off[d], 1);
    g_eidx[pos] = s;
    g_ew[pos] = g_dinv[s];
}

// ---------------------------------------------------------------------------
// Input-space aggregation (CSR, zero atomics): aggx = Â·x  (96-wide).
// One warp per dst; lanes 0..23 each own one float4. Edge loop unrolled x2
// (the x4 variant regressed ~20us via L1tex-queue contention — R11/R12
// post-mortem; MLP_p1 was pushed past the per-SM queue sweet spot).
// ---------------------------------------------------------------------------
__global__ void aggx_csr_kernel(const float* __restrict__ x, int N) {
    int gid = blockIdx.x * blockDim.x + threadIdx.x;
    int d = gid >> 5;
    int lane = gid & 31;
    if (d >= N || lane >= 24) return;

    int end = g_off[d];
    int beg = end - g_cnt[d];

    float4 acc0 = make_float4(0.f, 0.f, 0.f, 0.f);
    float4 acc1 = make_float4(0.f, 0.f, 0.f, 0.f);
    int j = beg;
    for (; j + 1 < end; j += 2) {
        int s0 = g_eidx[j], s1 = g_eidx[j + 1];
        float w0 = g_ew[j], w1 = g_ew[j + 1];
        float4 v0 = *(const float4*)(x + (size_t)s0 * FIN + lane * 4);
        float4 v1 = *(const float4*)(x + (size_t)s1 * FIN + lane * 4);
        acc0.x = fmaf(v0.x, w0, acc0.x);
        acc0.y = fmaf(v0.y, w0, acc0.y);
        acc0.z = fmaf(v0.z, w0, acc0.z);
        acc0.w = fmaf(v0.w, w0, acc0.w);
        acc1.x = fmaf(v1.x, w1, acc1.x);
        acc1.y = fmaf(v1.y, w1, acc1.y);
        acc1.z = fmaf(v1.z, w1, acc1.z);
        acc1.w = fmaf(v1.w, w1, acc1.w);
    }
    if (j < end) {
        int s0 = g_eidx[j];
        float w0 = g_ew[j];
        float4 v0 = *(const float4*)(x + (size_t)s0 * FIN + lane * 4);
        acc0.x = fmaf(v0.x, w0, acc0.x);
        acc0.y = fmaf(v0.y, w0, acc0.y);
        acc0.z = fmaf(v0.z, w0, acc0.z);
        acc0.w = fmaf(v0.w, w0, acc0.w);
    }
    acc0.x += acc1.x; acc0.y += acc1.y; acc0.z += acc1.z; acc0.w += acc1.w;

    float dd = g_dinv[d];
    float dd2 = dd * dd;
    float4 xd = *(const float4*)(x + (size_t)d * FIN + lane * 4);
    float4 r;
    r.x = fmaf(acc0.x, dd, xd.x * dd2);
    r.y = fmaf(acc0.y, dd, xd.y * dd2);
    r.z = fmaf(acc0.z, dd, xd.z * dd2);
    r.w = fmaf(acc0.w, dd, xd.w * dd2);
    g_aggx_4[(size_t)d * 24 + lane] = r;
}

// ---------------------------------------------------------------------------
// GEMM1 (TF32): h1b[N,128] = relu(aggx[N,96] @ W1[96,128] + b1); also emb.
// ---------------------------------------------------------------------------
__global__ void gemm1_tc_kernel(const float* __restrict__ W1,
                                const float* __restrict__ b1,
                                float* __restrict__ emb, int N) {
    __shared__ __align__(16) uint32_t Xs[128][36];
    __shared__ __align__(16) uint32_t Ws[32][132];
    const int tid = threadIdx.x;
    const int wid = tid >> 5;
    const int lane = tid & 31;
    const int gidl = lane >> 2;
    const int tig = lane & 3;
    const int warp_m = (wid >> 1) * 32;
    const int warp_n = (wid & 1) * 64;
    const int rowBase = blockIdx.x * 128;

    float acc[2][8][4];
#pragma unroll
    for (int mt = 0; mt < 2; mt++)
#pragma unroll
        for (int nt = 0; nt < 8; nt++)
#pragma unroll
            for (int i = 0; i < 4; i++) acc[mt][nt][i] = 0.0f;

    for (int k0 = 0; k0 < FIN; k0 += 32) {
#pragma unroll
        for (int t = tid; t < 1024; t += 256) {
            int r = t >> 3, c = (t & 7) * 4;
            int gr = rowBase + r;
            float4 v = make_float4(0.f, 0.f, 0.f, 0.f);
            if (gr < N) v = *(const float4*)(g_aggx + (size_t)gr * FIN + k0 + c);
            Xs[r][c + 0] = f2tf32(v.x);
            Xs[r][c + 1] = f2tf32(v.y);
            Xs[r][c + 2] = f2tf32(v.z);
            Xs[r][c + 3] = f2tf32(v.w);
        }
#pragma unroll
        for (int t = tid; t < 1024; t += 256) {
            int r = t >> 5, c = (t & 31) * 4;
            float4 v = *(const float4*)(W1 + (size_t)(k0 + r) * HID + c);
            Ws[r][c + 0] = f2tf32(v.x);
            Ws[r][c + 1] = f2tf32(v.y);
            Ws[r][c + 2] = f2tf32(v.z);
            Ws[r][c + 3] = f2tf32(v.w);
        }
        __syncthreads();

#pragma unroll
        for (int kk = 0; kk < 4; kk++) {
            int k8 = kk * 8;
            uint32_t a[2][4];
#pragma unroll
            for (int mt = 0; mt < 2; mt++) {
                int mb = warp_m + mt * 16;
                a[mt][0] = Xs[mb + gidl][k8 + tig];
                a[mt][1] = Xs[mb + gidl + 8][k8 + tig];
                a[mt][2] = Xs[mb + gidl][k8 + tig + 4];
                a[mt][3] = Xs[mb + gidl + 8][k8 + tig + 4];
            }
#pragma unroll
            for (int nt = 0; nt < 8; nt++) {
                int nb = warp_n + nt * 8;
                uint32_t b0 = Ws[k8 + tig][nb + gidl];
                uint32_t b1v = Ws[k8 + tig + 4][nb + gidl];
                mma_tf32(acc[0][nt], a[0], b0, b1v);
                mma_tf32(acc[1][nt], a[1], b0, b1v);
            }
        }
        __syncthreads();
    }

#pragma unroll
    for (int mt = 0; mt < 2; mt++) {
#pragma unroll
        for (int nt = 0; nt < 8; nt++) {
            int col = warp_n + nt * 8 + 2 * tig;
            float2 bb = *(const float2*)(b1 + col);
            int r0 = rowBase + warp_m + mt * 16 + gidl;
            if (r0 < N) {
                float2 v = make_float2(fmaxf(acc[mt][nt][0] + bb.x, 0.f),
                                       fmaxf(acc[mt][nt][1] + bb.y, 0.f));
                *(float2*)(g_h1b + (size_t)r0 * HID + col) = v;
                if (emb) *(float2*)(emb + (size_t)r0 * HID + col) = v;
            }
            if (r0 + 8 < N) {
                float2 v = make_float2(fmaxf(acc[mt][nt][2] + bb.x, 0.f),
                                       fmaxf(acc[mt][nt][3] + bb.y, 0.f));
                *(float2*)(g_h1b + (size_t)(r0 + 8) * HID + col) = v;
                if (emb) *(float2*)(emb + (size_t)(r0 + 8) * HID + col) = v;
            }
        }
    }
}

// ---------------------------------------------------------------------------
// GEMM2 (TF32): g_h2[N,64] = g_h1b[N,128] @ W2[128,64]
// ---------------------------------------------------------------------------
__global__ void gemm2_tc_kernel(const float* __restrict__ W2, int N) {
    __shared__ __align__(16) uint32_t Xs[128][36];
    __shared__ __align__(16) uint32_t Ws[32][68];
    const int tid = threadIdx.x;
    const int wid = tid >> 5;
    const int lane = tid & 31;
    const int gidl = lane >> 2;
    const int tig = lane & 3;
    const int warp_m = wid * 16;
    const int rowBase = blockIdx.x * 128;

    float acc[8][4];
#pragma unroll
    for (int nt = 0; nt < 8; nt++)
#pragma unroll
        for (int i = 0; i < 4; i++) acc[nt][i] = 0.0f;

    for (int k0 = 0; k0 < HID; k0 += 32) {
#pragma unroll
        for (int t = tid; t < 1024; t += 256) {
            int r = t >> 3, c = (t & 7) * 4;
            int gr = rowBase + r;
            float4 v = make_float4(0.f, 0.f, 0.f, 0.f);
            if (gr < N) v = *(const float4*)(g_h1b + (size_t)gr * HID + k0 + c);
            Xs[r][c + 0] = f2tf32(v.x);
            Xs[r][c + 1] = f2tf32(v.y);
            Xs[r][c + 2] = f2tf32(v.z);
            Xs[r][c + 3] = f2tf32(v.w);
        }
#pragma unroll
        for (int t = tid; t < 512; t += 256) {
            int r = t >> 4, c = (t & 15) * 4;
            float4 v = *(const float4*)(W2 + (size_t)(k0 + r) * COUT + c);
            Ws[r][c + 0] = f2tf32(v.x);
            Ws[r][c + 1] = f2tf32(v.y);
            Ws[r][c + 2] = f2tf32(v.z);
            Ws[r][c + 3] = f2tf32(v.w);
        }
        __syncthreads();

#pragma unroll
        for (int kk = 0; kk < 4; kk++) {
            int k8 = kk * 8;
            uint32_t a[4];
            a[0] = Xs[warp_m + gidl][k8 + tig];
            a[1] = Xs[warp_m + gidl + 8][k8 + tig];
            a[2] = Xs[warp_m + gidl][k8 + tig + 4];
            a[3] = Xs[warp_m + gidl + 8][k8 + tig + 4];
#pragma unroll
            for (int nt = 0; nt < 8; nt++) {
                int nb = nt * 8;
                uint32_t b0 = Ws[k8 + tig][nb + gidl];
                uint32_t b1 = Ws[k8 + tig + 4][nb + gidl];
                mma_tf32(acc[nt], a, b0, b1);
            }
        }
        __syncthreads();
    }

#pragma unroll
    for (int nt = 0; nt < 8; nt++) {
        int col = nt * 8 + 2 * tig;
        int r0 = rowBase + warp_m + gidl;
        if (r0 < N)
            *(float2*)(g_h2 + (size_t)r0 * COUT + col) =
                make_float2(acc[nt][0], acc[nt][1]);
        if (r0 + 8 < N)
            *(float2*)(g_h2 + (size_t)(r0 + 8) * COUT + col) =
                make_float2(acc[nt][2], acc[nt][3]);
    }
}

// ---------------------------------------------------------------------------
// Layer-2 aggregation (CSR) + bias + fused warp log_softmax. Unrolled x2.
// ---------------------------------------------------------------------------
__global__ void agg2_csr_kernel(const float* __restrict__ b2,
                                float* __restrict__ out, int N) {
    int gid = blockIdx.x * blockDim.x + threadIdx.x;
    int d = gid >> 5;
    int lane = gid & 31;
    if (d >= N) return;

    int end = g_off[d];
    int beg = end - g_cnt[d];

    float2 acc0 = make_float2(0.f, 0.f);
    float2 acc1 = make_float2(0.f, 0.f);
    int j = beg;
    for (; j + 1 < end; j += 2) {
        int s0 = g_eidx[j], s1 = g_eidx[j + 1];
        float w0 = g_ew[j], w1 = g_ew[j + 1];
        float2 v0 = *(const float2*)(g_h2 + (size_t)s0 * COUT + lane * 2);
        float2 v1 = *(const float2*)(g_h2 + (size_t)s1 * COUT + lane * 2);
        acc0.x = fmaf(v0.x, w0, acc0.x);
        acc0.y = fmaf(v0.y, w0, acc0.y);
        acc1.x = fmaf(v1.x, w1, acc1.x);
        acc1.y = fmaf(v1.y, w1, acc1.y);
    }
    if (j < end) {
        int s0 = g_eidx[j];
        float w0 = g_ew[j];
        float2 v0 = *(const float2*)(g_h2 + (size_t)s0 * COUT + lane * 2);
        acc0.x = fmaf(v0.x, w0, acc0.x);
        acc0.y = fmaf(v0.y, w0, acc0.y);
    }
    acc0.x += acc1.x; acc0.y += acc1.y;

    float dd = g_dinv[d];
    float dd2 = dd * dd;
    float2 hd = *(const float2*)(g_h2 + (size_t)d * COUT + lane * 2);
    float2 bb = *(const float2*)(b2 + lane * 2);
    float2 o;
    o.x = fmaf(acc0.x, dd, fmaf(hd.x, dd2, bb.x));
    o.y = fmaf(acc0.y, dd, fmaf(hd.y, dd2, bb.y));

    float m = fmaxf(o.x, o.y);
#pragma unroll
    for (int off = 16; off > 0; off >>= 1)
        m = fmaxf(m, __shfl_xor_sync(0xFFFFFFFFu, m, off));
    float sum = expf(o.x - m) + expf(o.y - m);
#pragma unroll
    for (int off = 16; off > 0; off >>= 1)
        sum += __shfl_xor_sync(0xFFFFFFFFu, sum, off);
    float l = logf(sum) + m;
    *(float2*)(out + (size_t)d * COUT + lane * 2) =
        make_float2(o.x - l, o.y - l);
}

// ---------------------------------------------------------------------------
extern "C" void kernel_launch(void* const* d_in, const int* in_sizes, int n_in,
                              void* d_out, int out_size) {
    const float* x  = (const float*)d_in[0];
    const float* W1 = (const float*)d_in[1];
    const float* b1 = (const float*)d_in[2];
    const float* W2 = (const float*)d_in[3];
    const float* b2 = (const float*)d_in[4];
    const void*  ei = d_in[5];

    const int H   = in_sizes[2];                 // 128
    const int Fin = in_sizes[1] / H;             // 96
    const int C   = in_sizes[4];                 // 64
    const int N   = in_sizes[0] / Fin;           // 100000
    const int E   = in_sizes[5] / 2;             // 800000

    float* out = (float*)d_out;
    float* emb = ((long long)out_size >= (long long)N * (C + H))
                     ? out + (size_t)N * C
                     : nullptr;

    const int T = 256;
    const int nblk = (N + 255) / 256;

    // Init + dtype detect, then convert+count (src/dst materialized once).
    init_detect_kernel<<<(N + T - 1) / T, T>>>((const unsigned*)ei, E, N);
    idx_convert_count_kernel<<<(E + T - 1) / T, T>>>(ei, E);

    // CSR build
    scanA_kernel<<<nblk, 256>>>(N);
    scanB_kernel<<<1, 512>>>(nblk);
    scanC_kernel<<<(N + T - 1) / T, T>>>(N);
    scatter_kernel<<<(E + T - 1) / T, T>>>(E);

    // Layer 1: aggregate in input space (96-wide), then GEMM with fused
    // bias+relu+embedding epilogue.
    aggx_csr_kernel<<<(int)(((long long)N * 32 + T - 1) / T), T>>>(x, N);
    gemm1_tc_kernel<<<(N + 127) / 128, 256>>>(W1, b1, emb, N);

    // Layer 2: GEMM then aggregate in output space (64-wide) with fused
    // bias + log_softmax.
    gemm2_tc_kernel<<<(N + 127) / 128, 256>>>(W2, N);
    agg2_csr_kernel<<<(int)(((long long)N * 32 + T - 1) / T), T>>>(b2, out, N);
}